// round 6
// baseline (speedup 1.0000x reference)
#include <cuda_runtime.h>
#include <math.h>

// ----------------------------------------------------------------------------
// qMT SPGR steady-state signal, 1M voxels. Two launches:
//   k1 (table): 4096-entry float2 G-table {G_i, G_{i+1}} over a FIXED
//       float-bit-space domain [1e-9, 1e-3]  (~log spacing, no minmax pass),
//       plus uniform scalar precompute.
//   k2 (voxel): 4 voxels/thread, float4 I/O, front-batched single-float2
//       table gathers, closed-form 2x2 Bloch-McConnell steady state with an
//       rsqrt-based eigen expm (shortest possible MUFU chain).
// ----------------------------------------------------------------------------

#define NTAB 4096
#define NINT 100
#define PI_F 3.14159265358979f

#define XLO 1e-9f
#define XHI 1e-3f

__device__ float2 g_tab2[NTAB];   // {G(x_i), G(x_{i+1})}
__device__ float4 g_scal;         // {tr, Wc, cos(exc), sin(exc)}

// ---------------------------------------------------------------------------
// Table kernel. Thread i computes G_i, stores tab2[i].x = G_i and
// tab2[i-1].y = G_i (so each entry holds its right neighbor too).
// ---------------------------------------------------------------------------
__global__ void __launch_bounds__(128) table_kernel(
    const float* __restrict__ tr_p,
    const float* __restrict__ exc_p,
    const float* __restrict__ mtfa_p,
    const float* __restrict__ mtoff_p,
    const float* __restrict__ mtdur_p)
{
    __shared__ float sw[NINT];   // sqrt(2/pi)*sin(th)*trap*h / term
    __shared__ float sc[NINT];   // 2*(2*pi*delta/term)^2

    const float delta = *mtoff_p;
    const int t = threadIdx.x;
    if (t < NINT) {
        const float h = (PI_F * 0.5f) / (float)(NINT - 1);
        float th = h * (float)t;
        float st = sinf(th);
        float ctt = cosf(th);
        float term = fabsf(fmaf(3.0f * ctt, ctt, -1.0f));
        term = fmaxf(term, 1e-6f);
        float trap = (t == 0 || t == NINT - 1) ? 0.5f : 1.0f;
        float invterm = 1.0f / term;
        sw[t] = 0.7978845608028654f * st * trap * h * invterm;
        float q = 2.0f * PI_F * delta * invterm;
        sc[t] = 2.0f * q * q;
    }
    __syncthreads();

    const int i = blockIdx.x * blockDim.x + t;
    const int B0 = __float_as_int(XLO);
    const int B1 = __float_as_int(XHI);
    const int STEP = (B1 - B0) / (NTAB - 1);
    if (i < NTAB) {
        float x  = __int_as_float(B0 + i * STEP);
        float x2 = x * x;
        float sum = 0.0f;
#pragma unroll 4
        for (int j = 0; j < NINT; j++)
            sum += sw[j] * __expf(-sc[j] * x2);
        float g = x * sum;
        g_tab2[i].x = g;
        if (i > 0) g_tab2[i - 1].y = g;
        if (i == NTAB - 1) g_tab2[i].y = g;   // unused (idx clamped), keep sane
    }

    if (i == 0) {
        float tr     = *tr_p;
        float exc    = (*exc_p) * (PI_F / 180.0f);
        float mt_rad = (*mtfa_p) * (PI_F / 180.0f);
        float mt_dur = *mtdur_p;
        float w1     = mt_rad / mt_dur;
        float Wc     = PI_F * (w1 * w1) * (mt_dur / tr);
        g_scal = make_float4(tr, Wc, cosf(exc), sinf(exc));
    }
}

// ---------------------------------------------------------------------------
// 2x2 Bloch-McConnell closed form (g already interpolated).
// ---------------------------------------------------------------------------
__device__ __forceinline__ float bm_compute(
    float f, float kmf, float R1f, float R1m, float g,
    float tr, float Wc, float ce, float se)
{
    const float W      = Wc * g;
    const float one_mf = 1.0f - f;
    const float kfr    = kmf * f * __frcp_rn(one_mf + 1e-9f);

    const float a = -(R1f + kfr);
    const float b = kmf;
    const float c = kfr;
    const float d = -(R1m + kmf + W);

    // E = expm(A*tr): eigenvalues m ± s.  q = p^2 + bt*ct > 0 strictly,
    // so one rsqrt gives both s = q*rsq and 1/s = rsq.
    const float at = a * tr, bt = b * tr, ct = c * tr, dtt = d * tr;
    const float m   = 0.5f * (at + dtt);
    const float p   = 0.5f * (at - dtt);
    const float q   = fmaf(p, p, bt * ct);
    const float rsq = rsqrtf(q);
    const float s   = q * rsq;
    const float e1  = __expf(m + s);
    const float e2  = __expf(m - s);
    const float u   = (e1 - e2) * 0.5f * rsq;   // e^m sinh(s)/s
    const float v   = 0.5f * (e1 + e2);         // e^m cosh(s)
    const float E11 = fmaf(u, p, v);
    const float E12 = u * bt;
    const float E21 = u * ct;
    const float E22 = fmaf(-u, p, v);

    // M* = -A^{-1} B ;  M_relax = (I - E) M*
    const float B0v = R1f * one_mf;
    const float B1v = R1m * f;
    const float det    = fmaf(a, d, -b * c);
    const float invdet = __frcp_rn(det);
    const float Ms0 = -(d * B0v - b * B1v) * invdet;
    const float Ms1 = -(a * B1v - c * B0v) * invdet;
    const float r0 = (1.0f - E11) * Ms0 - E12 * Ms1;
    const float r1 = (1.0f - E22) * Ms1 - E21 * Ms0;

    // Solve (I - E Q) x = M_relax,  Q = diag(cos(exc), 1)
    const float M00 = 1.0f - E11 * ce;
    const float M01 = -E12;
    const float M10 = -E21 * ce;
    const float M11 = 1.0f - E22;
    const float dM  = fmaf(M00, M11, -M01 * M10);
    const float x0  = (M11 * r0 - M01 * r1) * __frcp_rn(dM);

    return x0 * se;
}

__device__ __forceinline__ float table_lerp(float t2m, int B0, float inv_step) {
    float pos = (float)(__float_as_int(t2m) - B0) * inv_step;
    pos = fminf(fmaxf(pos, 0.0f), (float)(NTAB - 1) - 0.001f);
    int idx = (int)pos;
    float fr = pos - (float)idx;
    float2 gv = __ldg(&g_tab2[idx]);
    return fmaf(fr, gv.y - gv.x, gv.x);
}

__global__ void __launch_bounds__(256) voxel_kernel(
    const float* __restrict__ f_in,
    const float* __restrict__ kmf_in,
    const float* __restrict__ r1f_in,
    const float* __restrict__ r1m_in,
    const float* __restrict__ t2m_in,
    float* __restrict__ out,
    int n)
{
    const float4 sc = g_scal;
    const float tr = sc.x, Wc = sc.y, ce = sc.z, se = sc.w;

    const int B0 = __float_as_int(XLO);
    const int B1 = __float_as_int(XHI);
    const int STEP = (B1 - B0) / (NTAB - 1);
    const float inv_step = 1.0f / (float)STEP;

    const int base = (blockIdx.x * blockDim.x + threadIdx.x) * 4;
    if (base >= n) return;

    if (base + 3 < n) {
        const float4 vt = *(const float4*)(t2m_in + base);
        const float4 vf = *(const float4*)(f_in   + base);
        const float4 vk = *(const float4*)(kmf_in + base);
        const float4 va = *(const float4*)(r1f_in + base);
        const float4 vb = *(const float4*)(r1m_in + base);

        // Front-batched gathers: 4 independent 8B table loads in flight.
        float g0 = table_lerp(vt.x, B0, inv_step);
        float g1 = table_lerp(vt.y, B0, inv_step);
        float g2 = table_lerp(vt.z, B0, inv_step);
        float g3 = table_lerp(vt.w, B0, inv_step);

        float4 r;
        r.x = bm_compute(vf.x, vk.x, va.x, vb.x, g0, tr, Wc, ce, se);
        r.y = bm_compute(vf.y, vk.y, va.y, vb.y, g1, tr, Wc, ce, se);
        r.z = bm_compute(vf.z, vk.z, va.z, vb.z, g2, tr, Wc, ce, se);
        r.w = bm_compute(vf.w, vk.w, va.w, vb.w, g3, tr, Wc, ce, se);
        *(float4*)(out + base) = r;
    } else {
        for (int i = base; i < n; i++) {
            float g = table_lerp(t2m_in[i], B0, inv_step);
            out[i] = bm_compute(f_in[i], kmf_in[i], r1f_in[i], r1m_in[i], g,
                                tr, Wc, ce, se);
        }
    }
}

extern "C" void kernel_launch(void* const* d_in, const int* in_sizes, int n_in,
                              void* d_out, int out_size) {
    // metadata order: f, k_mf, R1_f, R1_m, T2_f, T2_m, tr, exc_fa, mt_fa,
    //                 mt_offset, mt_dur
    const float* f_in    = (const float*)d_in[0];
    const float* kmf_in  = (const float*)d_in[1];
    const float* r1f_in  = (const float*)d_in[2];
    const float* r1m_in  = (const float*)d_in[3];
    const float* t2m_in  = (const float*)d_in[5];
    const float* tr_p    = (const float*)d_in[6];
    const float* exc_p   = (const float*)d_in[7];
    const float* mtfa_p  = (const float*)d_in[8];
    const float* mtoff_p = (const float*)d_in[9];
    const float* mtdur_p = (const float*)d_in[10];
    float* out = (float*)d_out;
    const int n = in_sizes[5];

    table_kernel<<<NTAB / 128, 128>>>(tr_p, exc_p, mtfa_p, mtoff_p, mtdur_p);

    const int threads = (n + 3) / 4;
    voxel_kernel<<<(threads + 255) / 256, 256>>>(f_in, kmf_in, r1f_in, r1m_in,
                                                 t2m_in, out, n);
}

// round 7
// speedup vs baseline: 1.0205x; 1.0205x over previous
#include <cuda_runtime.h>
#include <math.h>

// ----------------------------------------------------------------------------
// qMT SPGR steady-state signal, 1M voxels. Two launches:
//   k1 (table): 1024-entry float2 G-table {G_i, G_{i+1}} over a FIXED
//       float-bit-space domain [1e-7, 1e-4] (~log spacing, no minmax pass),
//       plus uniform scalar precompute.
//   k2 (voxel): 8 voxels/thread (single wave, high ILP), float4 I/O,
//       front-batched float2 table gathers, closed-form 2x2 Bloch-McConnell
//       with approx-MUFU reciprocals (rcp.approx) and rsqrt-based expm.
// ----------------------------------------------------------------------------

#define NTAB 1024
#define NINT 100
#define PI_F 3.14159265358979f

#define XLO 1e-7f
#define XHI 1e-4f

__device__ float2 g_tab2[NTAB];   // {G(x_i), G(x_{i+1})}
__device__ float4 g_scal;         // {tr, Wc, cos(exc), sin(exc)}

__device__ __forceinline__ float rcp_fast(float x) {
    float r;
    asm("rcp.approx.ftz.f32 %0, %1;" : "=f"(r) : "f"(x));
    return r;
}

// ---------------------------------------------------------------------------
// Table kernel. Thread i computes G_i, stores tab2[i].x = G_i and
// tab2[i-1].y = G_i.
// ---------------------------------------------------------------------------
__global__ void __launch_bounds__(128) table_kernel(
    const float* __restrict__ tr_p,
    const float* __restrict__ exc_p,
    const float* __restrict__ mtfa_p,
    const float* __restrict__ mtoff_p,
    const float* __restrict__ mtdur_p)
{
    __shared__ float sw[NINT];   // sqrt(2/pi)*sin(th)*trap*h / term
    __shared__ float sc[NINT];   // 2*(2*pi*delta/term)^2

    const float delta = *mtoff_p;
    const int t = threadIdx.x;
    if (t < NINT) {
        const float h = (PI_F * 0.5f) / (float)(NINT - 1);
        float th = h * (float)t;
        float st = sinf(th);
        float ctt = cosf(th);
        float term = fabsf(fmaf(3.0f * ctt, ctt, -1.0f));
        term = fmaxf(term, 1e-6f);
        float trap = (t == 0 || t == NINT - 1) ? 0.5f : 1.0f;
        float invterm = 1.0f / term;
        sw[t] = 0.7978845608028654f * st * trap * h * invterm;
        float q = 2.0f * PI_F * delta * invterm;
        sc[t] = 2.0f * q * q;
    }
    __syncthreads();

    const int i = blockIdx.x * blockDim.x + t;
    const int B0 = __float_as_int(XLO);
    const int B1 = __float_as_int(XHI);
    const int STEP = (B1 - B0) / (NTAB - 1);
    if (i < NTAB) {
        float x  = __int_as_float(B0 + i * STEP);
        float x2 = x * x;
        float sum = 0.0f;
#pragma unroll 4
        for (int j = 0; j < NINT; j++)
            sum += sw[j] * __expf(-sc[j] * x2);
        float g = x * sum;
        g_tab2[i].x = g;
        if (i > 0) g_tab2[i - 1].y = g;
        if (i == NTAB - 1) g_tab2[i].y = g;   // idx clamped below; keep sane
    }

    if (i == 0) {
        float tr     = *tr_p;
        float exc    = (*exc_p) * (PI_F / 180.0f);
        float mt_rad = (*mtfa_p) * (PI_F / 180.0f);
        float mt_dur = *mtdur_p;
        float w1     = mt_rad / mt_dur;
        float Wc     = PI_F * (w1 * w1) * (mt_dur / tr);
        g_scal = make_float4(tr, Wc, cosf(exc), sinf(exc));
    }
}

// ---------------------------------------------------------------------------
// 2x2 Bloch-McConnell closed form (g already interpolated).
// ---------------------------------------------------------------------------
__device__ __forceinline__ float bm_compute(
    float f, float kmf, float R1f, float R1m, float g,
    float tr, float Wc, float ce, float se)
{
    const float W      = Wc * g;
    const float one_mf = 1.0f - f;
    const float kfr    = kmf * f * rcp_fast(one_mf + 1e-9f);

    const float a = -(R1f + kfr);
    const float b = kmf;
    const float c = kfr;
    const float d = -(R1m + kmf + W);

    // E = expm(A*tr): eigenvalues m ± s.  q = p^2 + bt*ct > 0 strictly,
    // so one rsqrt gives both s = q*rsq and 1/s = rsq.
    const float at = a * tr, bt = b * tr, ct = c * tr, dtt = d * tr;
    const float m   = 0.5f * (at + dtt);
    const float p   = 0.5f * (at - dtt);
    const float q   = fmaf(p, p, bt * ct);
    const float rsq = rsqrtf(q);
    const float s   = q * rsq;
    const float e1  = __expf(m + s);
    const float e2  = __expf(m - s);
    const float u   = (e1 - e2) * 0.5f * rsq;   // e^m sinh(s)/s
    const float v   = 0.5f * (e1 + e2);         // e^m cosh(s)
    const float E11 = fmaf(u, p, v);
    const float E12 = u * bt;
    const float E21 = u * ct;
    const float E22 = fmaf(-u, p, v);

    // M* = -A^{-1} B ;  M_relax = (I - E) M*
    const float B0v = R1f * one_mf;
    const float B1v = R1m * f;
    const float det    = fmaf(a, d, -b * c);
    const float invdet = rcp_fast(det);
    const float Ms0 = -(d * B0v - b * B1v) * invdet;
    const float Ms1 = -(a * B1v - c * B0v) * invdet;
    const float r0 = (1.0f - E11) * Ms0 - E12 * Ms1;
    const float r1 = (1.0f - E22) * Ms1 - E21 * Ms0;

    // Solve (I - E Q) x = M_relax,  Q = diag(cos(exc), 1)
    const float M00 = 1.0f - E11 * ce;
    const float M01 = -E12;
    const float M10 = -E21 * ce;
    const float M11 = 1.0f - E22;
    const float dM  = fmaf(M00, M11, -M01 * M10);
    const float x0  = (M11 * r0 - M01 * r1) * rcp_fast(dM);

    return x0 * se;
}

__device__ __forceinline__ float table_lerp(float t2m, int B0, float inv_step) {
    float pos = (float)(__float_as_int(t2m) - B0) * inv_step;
    pos = fminf(fmaxf(pos, 0.0f), (float)(NTAB - 1) - 0.001f);
    int idx = (int)pos;
    float fr = pos - (float)idx;
    float2 gv = __ldg(&g_tab2[idx]);
    return fmaf(fr, gv.y - gv.x, gv.x);
}

__global__ void __launch_bounds__(256, 4) voxel_kernel(
    const float* __restrict__ f_in,
    const float* __restrict__ kmf_in,
    const float* __restrict__ r1f_in,
    const float* __restrict__ r1m_in,
    const float* __restrict__ t2m_in,
    float* __restrict__ out,
    int n)
{
    const float4 sc = g_scal;
    const float tr = sc.x, Wc = sc.y, ce = sc.z, se = sc.w;

    const int B0 = __float_as_int(XLO);
    const int B1 = __float_as_int(XHI);
    const int STEP = (B1 - B0) / (NTAB - 1);
    const float inv_step = 1.0f / (float)STEP;

    const int base = (blockIdx.x * blockDim.x + threadIdx.x) * 8;
    if (base >= n) return;

    if (base + 7 < n) {
        // Front-batch all loads: 10 coalesced float4 + 8 small gathers.
        const float4 vt0 = *(const float4*)(t2m_in + base);
        const float4 vt1 = *(const float4*)(t2m_in + base + 4);
        const float4 vf0 = *(const float4*)(f_in   + base);
        const float4 vf1 = *(const float4*)(f_in   + base + 4);
        const float4 vk0 = *(const float4*)(kmf_in + base);
        const float4 vk1 = *(const float4*)(kmf_in + base + 4);
        const float4 va0 = *(const float4*)(r1f_in + base);
        const float4 va1 = *(const float4*)(r1f_in + base + 4);
        const float4 vb0 = *(const float4*)(r1m_in + base);
        const float4 vb1 = *(const float4*)(r1m_in + base + 4);

        float g0 = table_lerp(vt0.x, B0, inv_step);
        float g1 = table_lerp(vt0.y, B0, inv_step);
        float g2 = table_lerp(vt0.z, B0, inv_step);
        float g3 = table_lerp(vt0.w, B0, inv_step);
        float g4 = table_lerp(vt1.x, B0, inv_step);
        float g5 = table_lerp(vt1.y, B0, inv_step);
        float g6 = table_lerp(vt1.z, B0, inv_step);
        float g7 = table_lerp(vt1.w, B0, inv_step);

        float4 r0, r1;
        r0.x = bm_compute(vf0.x, vk0.x, va0.x, vb0.x, g0, tr, Wc, ce, se);
        r0.y = bm_compute(vf0.y, vk0.y, va0.y, vb0.y, g1, tr, Wc, ce, se);
        r0.z = bm_compute(vf0.z, vk0.z, va0.z, vb0.z, g2, tr, Wc, ce, se);
        r0.w = bm_compute(vf0.w, vk0.w, va0.w, vb0.w, g3, tr, Wc, ce, se);
        r1.x = bm_compute(vf1.x, vk1.x, va1.x, vb1.x, g4, tr, Wc, ce, se);
        r1.y = bm_compute(vf1.y, vk1.y, va1.y, vb1.y, g5, tr, Wc, ce, se);
        r1.z = bm_compute(vf1.z, vk1.z, va1.z, vb1.z, g6, tr, Wc, ce, se);
        r1.w = bm_compute(vf1.w, vk1.w, va1.w, vb1.w, g7, tr, Wc, ce, se);
        *(float4*)(out + base)     = r0;
        *(float4*)(out + base + 4) = r1;
    } else {
        for (int i = base; i < n; i++) {
            float g = table_lerp(t2m_in[i], B0, inv_step);
            out[i] = bm_compute(f_in[i], kmf_in[i], r1f_in[i], r1m_in[i], g,
                                tr, Wc, ce, se);
        }
    }
}

extern "C" void kernel_launch(void* const* d_in, const int* in_sizes, int n_in,
                              void* d_out, int out_size) {
    // metadata order: f, k_mf, R1_f, R1_m, T2_f, T2_m, tr, exc_fa, mt_fa,
    //                 mt_offset, mt_dur
    const float* f_in    = (const float*)d_in[0];
    const float* kmf_in  = (const float*)d_in[1];
    const float* r1f_in  = (const float*)d_in[2];
    const float* r1m_in  = (const float*)d_in[3];
    const float* t2m_in  = (const float*)d_in[5];
    const float* tr_p    = (const float*)d_in[6];
    const float* exc_p   = (const float*)d_in[7];
    const float* mtfa_p  = (const float*)d_in[8];
    const float* mtoff_p = (const float*)d_in[9];
    const float* mtdur_p = (const float*)d_in[10];
    float* out = (float*)d_out;
    const int n = in_sizes[5];

    table_kernel<<<NTAB / 128, 128>>>(tr_p, exc_p, mtfa_p, mtoff_p, mtdur_p);

    const int threads = (n + 7) / 8;
    voxel_kernel<<<(threads + 255) / 256, 256>>>(f_in, kmf_in, r1f_in, r1m_in,
                                                 t2m_in, out, n);
}

// round 9
// speedup vs baseline: 1.1785x; 1.1549x over previous
#include <cuda_runtime.h>
#include <math.h>

// ----------------------------------------------------------------------------
// qMT SPGR steady-state signal, 1M voxels. Two launches:
//   k1 (table): warp-per-entry 1024-entry float2 G-table {G_i, G_{i+1}} over
//       FIXED float-bit-space domain [1e-7, 1e-4]; lanes split the 100-point
//       trapezoid, shfl-reduce. + uniform scalar precompute.
//   k2 (voxel): 2 voxels/thread, high occupancy (36-reg cap), minimal-op
//       closed-form 2x2 Bloch-McConnell with approx-MUFU recip/rsqrt.
// ----------------------------------------------------------------------------

#define NTAB 1024
#define NINT 100
#define PI_F 3.14159265358979f

#define XLO 1e-7f
#define XHI 1e-4f

__device__ float2 g_tab2[NTAB];   // {G(x_i), G(x_{i+1})}
__device__ float  g_scal8[8];     // {tr_half, tr2, tr, Wc, ce, se, -, -}

__device__ __forceinline__ float rcp_fast(float x) {
    float r;
    asm("rcp.approx.ftz.f32 %0, %1;" : "=f"(r) : "f"(x));
    return r;
}

// ---------------------------------------------------------------------------
// Table kernel: one warp per table entry. Lane j handles theta points
// j, j+32, j+64, j+96; warp shfl-reduce gives the trapezoid sum.
// ---------------------------------------------------------------------------
__global__ void __launch_bounds__(256) table_kernel(
    const float* __restrict__ tr_p,
    const float* __restrict__ exc_p,
    const float* __restrict__ mtfa_p,
    const float* __restrict__ mtoff_p,
    const float* __restrict__ mtdur_p)
{
    const float delta = *mtoff_p;
    const int lane = threadIdx.x & 31;
    const int wid  = threadIdx.x >> 5;
    const int entry = blockIdx.x * 8 + wid;     // 8 warps/block

    const int B0 = __float_as_int(XLO);
    const int B1 = __float_as_int(XHI);
    const int STEP = (B1 - B0) / (NTAB - 1);
    const float x  = __int_as_float(B0 + entry * STEP);
    const float x2 = x * x;

    const float h = (PI_F * 0.5f) / (float)(NINT - 1);
    float sum = 0.0f;
#pragma unroll
    for (int k = 0; k < 4; k++) {
        int j = lane + 32 * k;
        if (j < NINT) {
            float th = h * (float)j;
            float st = sinf(th);
            float ctt = cosf(th);
            float term = fabsf(fmaf(3.0f * ctt, ctt, -1.0f));
            term = fmaxf(term, 1e-6f);
            float invterm = 1.0f / term;
            float trap = (j == 0 || j == NINT - 1) ? 0.5f : 1.0f;
            float w = 0.7978845608028654f * st * trap * h * invterm;
            float q = 2.0f * PI_F * delta * invterm;
            float c = 2.0f * q * q;
            sum += w * __expf(-c * x2);
        }
    }
#pragma unroll
    for (int o = 16; o > 0; o >>= 1)
        sum += __shfl_xor_sync(0xFFFFFFFFu, sum, o);

    if (lane == 0) {
        float g = x * sum;
        g_tab2[entry].x = g;
        if (entry > 0) g_tab2[entry - 1].y = g;
        if (entry == NTAB - 1) g_tab2[entry].y = g;   // idx clamped; keep sane
    }

    if (blockIdx.x == 0 && threadIdx.x == 0) {
        float tr     = *tr_p;
        float exc    = (*exc_p) * (PI_F / 180.0f);
        float mt_rad = (*mtfa_p) * (PI_F / 180.0f);
        float mt_dur = *mtdur_p;
        float w1     = mt_rad / mt_dur;
        float Wc     = PI_F * (w1 * w1) * (mt_dur / tr);
        g_scal8[0] = 0.5f * tr;
        g_scal8[1] = tr * tr;
        g_scal8[2] = tr;
        g_scal8[3] = Wc;
        g_scal8[4] = cosf(exc);
        g_scal8[5] = sinf(exc);
    }
}

// ---------------------------------------------------------------------------
// Minimal-op 2x2 Bloch-McConnell closed form (g already interpolated).
// ---------------------------------------------------------------------------
__device__ __forceinline__ float bm_compute(
    float f, float kmf, float R1f, float R1m, float g,
    float trh, float tr2, float tr, float Wc, float ce, float se)
{
    const float W      = Wc * g;
    const float one_mf = 1.0f - f;
    const float kfr    = kmf * f * rcp_fast(one_mf + 1e-9f);

    const float a = -(R1f + kfr);
    const float b = kmf;
    const float c = kfr;
    const float d = -(R1m + kmf + W);

    // E = expm(A*tr) via eigenvalues m +/- s (q > 0 strictly).
    const float m   = (a + d) * trh;
    const float p   = (a - d) * trh;
    const float bc  = b * c;
    const float q   = fmaf(p, p, bc * tr2);
    const float rsq = rsqrtf(q);
    const float s   = q * rsq;
    const float e1  = __expf(m + s);
    const float e2  = __expf(m - s);
    const float u   = (e1 - e2) * 0.5f * rsq;   // e^m sinh(s)/s  (per unit)
    const float v   = 0.5f * (e1 + e2);         // e^m cosh(s)
    const float E11 = fmaf(u, p, v);
    const float E22 = fmaf(-u, p, v);
    const float utr = u * tr;
    const float E12 = utr * b;
    const float E21 = utr * c;

    // Steady state: M_inf = M0 + A^{-1} (0, W*f)
    const float det    = fmaf(a, d, -bc);        // > 0
    const float t      = (W * f) * rcp_fast(det);
    const float Ms0    = fmaf(-b, t, one_mf);
    const float Ms1    = fmaf(a, t, f);

    // r = (I - E) M_inf
    const float r0 = fmaf(-E12, Ms1, fmaf(-E11, Ms0, Ms0));
    const float r1 = fmaf(-E21, Ms0, fmaf(-E22, Ms1, Ms1));

    // Solve (I - E Q) x = r, Q = diag(ce, 1):
    //   M00 = 1 - E11*ce, M01 = -E12, M10 = -E21*ce, M11 = 1 - E22
    const float M00 = fmaf(-E11, ce, 1.0f);
    const float M11 = 1.0f - E22;
    const float dM  = fmaf(M00, M11, -(E12 * E21) * ce);
    const float x0  = fmaf(M11, r0, E12 * r1) * rcp_fast(dM);

    return x0 * se;
}

__device__ __forceinline__ float table_lerp(float t2m, int B0, float inv_step) {
    float pos = (float)(__float_as_int(t2m) - B0) * inv_step;
    pos = fminf(fmaxf(pos, 0.0f), (float)(NTAB - 1) - 0.001f);
    int idx = (int)pos;
    float fr = pos - (float)idx;
    float2 gv = __ldg(&g_tab2[idx]);
    return fmaf(fr, gv.y - gv.x, gv.x);
}

__global__ void __launch_bounds__(256, 7) voxel_kernel(
    const float* __restrict__ f_in,
    const float* __restrict__ kmf_in,
    const float* __restrict__ r1f_in,
    const float* __restrict__ r1m_in,
    const float* __restrict__ t2m_in,
    float* __restrict__ out,
    int n)
{
    const float trh = g_scal8[0];
    const float tr2 = g_scal8[1];
    const float tr  = g_scal8[2];
    const float Wc  = g_scal8[3];
    const float ce  = g_scal8[4];
    const float se  = g_scal8[5];

    const int B0 = __float_as_int(XLO);
    const int B1 = __float_as_int(XHI);
    const int STEP = (B1 - B0) / (NTAB - 1);
    const float inv_step = 1.0f / (float)STEP;

    const int base = (blockIdx.x * blockDim.x + threadIdx.x) * 2;
    if (base >= n) return;

    if (base + 1 < n) {
        const float2 vt = *(const float2*)(t2m_in + base);
        const float2 vf = *(const float2*)(f_in   + base);
        const float2 vk = *(const float2*)(kmf_in + base);
        const float2 va = *(const float2*)(r1f_in + base);
        const float2 vb = *(const float2*)(r1m_in + base);

        float g0 = table_lerp(vt.x, B0, inv_step);
        float g1 = table_lerp(vt.y, B0, inv_step);

        float2 r;
        r.x = bm_compute(vf.x, vk.x, va.x, vb.x, g0, trh, tr2, tr, Wc, ce, se);
        r.y = bm_compute(vf.y, vk.y, va.y, vb.y, g1, trh, tr2, tr, Wc, ce, se);
        *(float2*)(out + base) = r;
    } else {
        float g = table_lerp(t2m_in[base], B0, inv_step);
        out[base] = bm_compute(f_in[base], kmf_in[base], r1f_in[base],
                               r1m_in[base], g, trh, tr2, tr, Wc, ce, se);
    }
}

extern "C" void kernel_launch(void* const* d_in, const int* in_sizes, int n_in,
                              void* d_out, int out_size) {
    // metadata order: f, k_mf, R1_f, R1_m, T2_f, T2_m, tr, exc_fa, mt_fa,
    //                 mt_offset, mt_dur
    const float* f_in    = (const float*)d_in[0];
    const float* kmf_in  = (const float*)d_in[1];
    const float* r1f_in  = (const float*)d_in[2];
    const float* r1m_in  = (const float*)d_in[3];
    const float* t2m_in  = (const float*)d_in[5];
    const float* tr_p    = (const float*)d_in[6];
    const float* exc_p   = (const float*)d_in[7];
    const float* mtfa_p  = (const float*)d_in[8];
    const float* mtoff_p = (const float*)d_in[9];
    const float* mtdur_p = (const float*)d_in[10];
    float* out = (float*)d_out;
    const int n = in_sizes[5];

    table_kernel<<<NTAB / 8, 256>>>(tr_p, exc_p, mtfa_p, mtoff_p, mtdur_p);

    const int threads = (n + 1) / 2;
    voxel_kernel<<<(threads + 255) / 256, 256>>>(f_in, kmf_in, r1f_in, r1m_in,
                                                 t2m_in, out, n);
}